// round 4
// baseline (speedup 1.0000x reference)
#include <cuda_runtime.h>
#include <math.h>

// ----------------------------------------------------------------------------
// DSimilarity gradgrad: out[3i+a, 3j+b] = sum_{p: i1[p]=i, q: i2[q]=j}
//    gg(d1[p]-d2[q]) * u1[p,a] * u2[q,b]
// gg(x) = (inv_l2 - x^2 inv_l2^2) * exp(-0.5 x^2 inv_l2)
//
// Deterministic counting-sort of pairs into per-atom buckets, then one thread
// per output atom-pair (i,j) computes its dense 3x3 block over cnt1[i]*cnt2[j]
// (~64) combinations. Blocks map to 16x16 (i,j) tiles (decoded on-device from
// the true natoms) so bucket rows are L1-resident and reused 16x.
// No big intermediates, no FP atomics, deterministic summation order.
// ----------------------------------------------------------------------------

#define MAX_ATOMS 4096
#define MAXC      64          // bucket capacity (mean count ~8; tail << 64)
#define RTILE     4096        // shared tile for the stable-rank scan
#define TI        16          // output tile: TI x TJ atoms per block
#define TJ        16

__device__ int    g_na1;
__device__ int    g_na2;
__device__ int    g_cnt1[MAX_ATOMS];
__device__ int    g_cnt2[MAX_ATOMS];
__device__ float4 g_pair1[MAX_ATOMS * MAXC];   // (d, ux, uy, uz) bucketed by i1
__device__ float4 g_pair2[MAX_ATOMS * MAXC];   // bucketed by i2

// ---- K0: zero counts + derive natoms (scalar inputs if present, else sqrt) --
__global__ void k_init(const int* na1p, const int* na2p, int out_size) {
    int t = blockIdx.x * blockDim.x + threadIdx.x;
    if (t < MAX_ATOMS) {
        g_cnt1[t] = 0;
        g_cnt2[t] = 0;
    }
    if (t == 0) {
        int na1, na2;
        if (na1p != nullptr && na2p != nullptr) {
            na1 = *na1p;
            na2 = *na2p;
        } else {
            int tot = out_size / 9;
            int r = (int)(sqrtf((float)tot) + 0.5f);
            while (r > 0 && r * r > tot) r--;
            while ((r + 1) * (r + 1) <= tot) r++;
            na1 = r; na2 = r;
        }
        if (na1 < 1) na1 = 1;  if (na1 > MAX_ATOMS) na1 = MAX_ATOMS;
        if (na2 < 1) na2 = 1;  if (na2 > MAX_ATOMS) na2 = MAX_ATOMS;
        g_na1 = na1;
        g_na2 = na2;
    }
}

// ---- K1: histogram (integer atomics only; order-independent) ----
__global__ void k_count(const int* __restrict__ i1, const int* __restrict__ i2, int n) {
    int p = blockIdx.x * blockDim.x + threadIdx.x;
    if (p < n) {
        atomicAdd(&g_cnt1[i1[p]], 1);
        atomicAdd(&g_cnt2[i2[p]], 1);
    }
}

// ---- K2: deterministic stable rank + scatter into buckets ----
// rank(p) = #{p' < p : idx[p'] == idx[p]}, computed by scanning the index
// arrays through shared-memory tiles. Deterministic placement ->
// deterministic FP summation order downstream.
__global__ void k_scatter(const float* __restrict__ d1, const float* __restrict__ u1,
                          const int* __restrict__ i1,
                          const float* __restrict__ d2, const float* __restrict__ u2,
                          const int* __restrict__ i2, int n) {
    __shared__ int sh1[RTILE];
    __shared__ int sh2[RTILE];
    int p = blockIdx.x * blockDim.x + threadIdx.x;
    bool active = (p < n);
    int my1 = -1, my2 = -1;
    if (active) { my1 = i1[p]; my2 = i2[p]; }
    int r1 = 0, r2 = 0;

    for (int base = 0; base < n; base += RTILE) {
        int m = min(RTILE, n - base);
        __syncthreads();
        for (int t = threadIdx.x; t < m; t += blockDim.x) {
            sh1[t] = i1[base + t];
            sh2[t] = i2[base + t];
        }
        __syncthreads();
        int lim = p - base;
        if (lim > m) lim = m;
        if (lim < 0) lim = 0;
        #pragma unroll 8
        for (int t = 0; t < lim; t++) {
            r1 += (sh1[t] == my1) ? 1 : 0;
            r2 += (sh2[t] == my2) ? 1 : 0;
        }
    }

    if (active) {
        if (my1 >= 0 && my1 < MAX_ATOMS && r1 < MAXC) {
            g_pair1[my1 * MAXC + r1] =
                make_float4(d1[p], u1[3 * p + 0], u1[3 * p + 1], u1[3 * p + 2]);
        }
        if (my2 >= 0 && my2 < MAX_ATOMS && r2 < MAXC) {
            g_pair2[my2 * MAXC + r2] =
                make_float4(d2[p], u2[3 * p + 0], u2[3 * p + 1], u2[3 * p + 2]);
        }
    }
}

// ---- K3: fused compute. 1D grid of TIxTJ tile slots, decoded on-device. ----
// Each block owns a 16x16 (i,j) atom tile: 16 P rows + 16 Q rows (~32KB)
// stay L1-resident and are each reused 16x.
__global__ void __launch_bounds__(TI * TJ)
k_compute(const float* __restrict__ ls, float* __restrict__ out) {
    int na1 = g_na1;
    int na2 = g_na2;
    int tiles_j = (na2 + TJ - 1) / TJ;
    int tiles_i = (na1 + TI - 1) / TI;
    int tile = blockIdx.x;
    if (tile >= tiles_i * tiles_j) return;
    int tile_i = tile / tiles_j;
    int tile_j = tile - tile_i * tiles_j;

    int tx = threadIdx.x & (TJ - 1);         // j within tile
    int ty = threadIdx.x / TJ;               // i within tile
    int i = tile_i * TI + ty;
    int j = tile_j * TJ + tx;
    if (i >= na1 || j >= na2) return;

    float l = ls[0];
    float inv_l2 = 1.0f / (l * l);
    float neg_half_inv_l2 = -0.5f * inv_l2;

    int c1 = g_cnt1[i]; if (c1 > MAXC) c1 = MAXC;
    int c2 = g_cnt2[j]; if (c2 > MAXC) c2 = MAXC;

    const float4* __restrict__ P = &g_pair1[i * MAXC];
    const float4* __restrict__ Q = &g_pair2[j * MAXC];

    float a00 = 0.f, a01 = 0.f, a02 = 0.f;
    float a10 = 0.f, a11 = 0.f, a12 = 0.f;
    float a20 = 0.f, a21 = 0.f, a22 = 0.f;

    for (int a = 0; a < c1; a++) {
        float4 pa = P[a];
        #pragma unroll 4
        for (int b = 0; b < c2; b++) {
            float4 qb = Q[b];
            float diff = pa.x - qb.x;
            float d2s  = diff * diff;
            float tt   = d2s * inv_l2;
            float k    = __expf(neg_half_inv_l2 * d2s);
            float g    = (1.0f - tt) * inv_l2 * k;
            float gx = g * pa.y;
            float gy = g * pa.z;
            float gz = g * pa.w;
            a00 += gx * qb.y; a01 += gx * qb.z; a02 += gx * qb.w;
            a10 += gy * qb.y; a11 += gy * qb.z; a12 += gy * qb.w;
            a20 += gz * qb.y; a21 += gz * qb.z; a22 += gz * qb.w;
        }
    }

    int ld = 3 * na2;
    float* o0 = out + (3 * i + 0) * (long long)ld + 3 * j;
    float* o1 = o0 + ld;
    float* o2 = o1 + ld;
    o0[0] = a00; o0[1] = a01; o0[2] = a02;
    o1[0] = a10; o1[1] = a11; o1[2] = a12;
    o2[0] = a20; o2[1] = a21; o2[2] = a22;
}

// ----------------------------------------------------------------------------
// Inputs (metadata order): d1[N], u1[N*3], d2[N], u2[N*3], lengthscale[1],
//                          i1[N], i2[N], [natoms1], [natoms2]
// Output: float[natoms1*3 * natoms2*3]
// ----------------------------------------------------------------------------
extern "C" void kernel_launch(void* const* d_in, const int* in_sizes, int n_in,
                              void* d_out, int out_size) {
    const float* d1 = (const float*)d_in[0];
    const float* u1 = (const float*)d_in[1];
    const float* d2 = (const float*)d_in[2];
    const float* u2 = (const float*)d_in[3];
    const float* ls = (const float*)d_in[4];
    const int*   i1 = (const int*)d_in[5];
    const int*   i2 = (const int*)d_in[6];
    const int*   na1p = (n_in >= 9) ? (const int*)d_in[7] : nullptr;
    const int*   na2p = (n_in >= 9) ? (const int*)d_in[8] : nullptr;

    int n_pairs = in_sizes[0];          // element count of d1 == N_PAIRS
    int tot = out_size / 9;             // na1 * na2 (true product)

    // Upper bound on tile count for ANY (na1, na2) with na1*na2 = tot and
    // na <= MAX_ATOMS:
    //   ceil(na1/16)*ceil(na2/16) <= tot/256 + (na1+na2)/16 + 1
    //                             <= tot/256 + 2*MAX_ATOMS/16 + 1
    int max_tiles = (tot + TI * TJ - 1) / (TI * TJ) + 2 * MAX_ATOMS / 16 + 2;

    k_init<<<(MAX_ATOMS + 255) / 256, 256>>>(na1p, na2p, out_size);
    k_count<<<(n_pairs + 255) / 256, 256>>>(i1, i2, n_pairs);
    k_scatter<<<(n_pairs + 511) / 512, 512>>>(d1, u1, i1, d2, u2, i2, n_pairs);
    k_compute<<<max_tiles, TI * TJ>>>(ls, (float*)d_out);
}

// round 8
// speedup vs baseline: 1.9969x; 1.9969x over previous
#include <cuda_runtime.h>
#include <math.h>

// ----------------------------------------------------------------------------
// DSimilarity gradgrad: out[3i+a, 3j+b] = sum_{p: i1[p]=i, q: i2[q]=j}
//    gg(d1[p]-d2[q]) * u1[p,a] * u2[q,b]
// gg(x) = (inv_l2 - x^2 inv_l2^2) * exp(-0.5 x^2 inv_l2)
//
// k_prep    : parallel deterministic counting sort (8 warps x p-ranges,
//             packed per-warp histograms, cross-warp prefix, match_any ranks).
// k_compute : 16x16 atom tile per block; bucket rows staged in padded shared
//             memory (kills the 16-way L1 wavefront split measured in R4).
// ----------------------------------------------------------------------------

#define MAX_ATOMS  4096
#define MAXC       64          // bucket capacity (mean count ~8)
#define PREP_WARPS 8
#define TI         16
#define TJ         16

__device__ int    g_na1;
__device__ int    g_na2;
__device__ int    g_cnt1[MAX_ATOMS];
__device__ int    g_cnt2[MAX_ATOMS];
__device__ float4 g_pair1[MAX_ATOMS * MAXC];   // (d, ux, uy, uz) bucketed by i1
__device__ float4 g_pair2[MAX_ATOMS * MAXC];   // bucketed by i2

// ---- K1: deterministic bucket build. One block, 512 threads. ----
// hist[w][atom] packs (cnt1 low16 | cnt2 high16) for warp w's p-range.
__global__ void __launch_bounds__(512)
k_prep(const float* __restrict__ d1, const float* __restrict__ u1,
       const int* __restrict__ i1,
       const float* __restrict__ d2, const float* __restrict__ u2,
       const int* __restrict__ i2,
       int n, const int* na1p, const int* na2p, int out_size) {
    extern __shared__ unsigned int hist[];   // [PREP_WARPS][MAX_ATOMS]

    int tid = threadIdx.x;

    if (tid == 0) {
        int na1, na2;
        if (na1p != nullptr && na2p != nullptr) {
            na1 = *na1p;
            na2 = *na2p;
        } else {
            int tot = out_size / 9;
            int r = (int)(sqrtf((float)tot) + 0.5f);
            while (r > 0 && r * r > tot) r--;
            while ((r + 1) * (r + 1) <= tot) r++;
            na1 = r; na2 = r;
        }
        if (na1 < 1) na1 = 1;  if (na1 > MAX_ATOMS) na1 = MAX_ATOMS;
        if (na2 < 1) na2 = 1;  if (na2 > MAX_ATOMS) na2 = MAX_ATOMS;
        g_na1 = na1;
        g_na2 = na2;
    }

    for (int t = tid; t < PREP_WARPS * MAX_ATOMS; t += 512) hist[t] = 0u;
    __syncthreads();

    int wid  = tid >> 5;
    int lane = tid & 31;
    int range = (n + PREP_WARPS - 1) / PREP_WARPS;
    int start = wid * range;
    int end   = start + range; if (end > n) end = n;

    // ---- Phase 1: per-warp packed histograms (order-independent atomics) ----
    if (wid < PREP_WARPS) {
        unsigned int* h = &hist[wid * MAX_ATOMS];
        for (int p0 = start; p0 < end; p0 += 32) {
            int p = p0 + lane;
            if (p < end) {
                unsigned a1 = (unsigned)i1[p];
                unsigned a2 = (unsigned)i2[p];
                if (a1 < MAX_ATOMS) atomicAdd(&h[a1], 1u);
                if (a2 < MAX_ATOMS) atomicAdd(&h[a2], 0x10000u);
            }
        }
    }
    __syncthreads();

    // ---- Phase 2: exclusive prefix across warps per atom; totals to g_cnt ----
    for (int atom = tid; atom < MAX_ATOMS; atom += 512) {
        unsigned run1 = 0, run2 = 0;
        #pragma unroll
        for (int w = 0; w < PREP_WARPS; w++) {
            unsigned v = hist[w * MAX_ATOMS + atom];
            hist[w * MAX_ATOMS + atom] = run1 | (run2 << 16);
            run1 += v & 0xFFFFu;
            run2 += v >> 16;
        }
        g_cnt1[atom] = (int)run1;
        g_cnt2[atom] = (int)run2;
    }
    __syncthreads();

    // ---- Phase 3: deterministic placement (stable = ascending p) ----
    if (wid < PREP_WARPS) {
        unsigned int* h = &hist[wid * MAX_ATOMS];
        for (int p0 = start; p0 < end; p0 += 32) {
            int p = p0 + lane;
            bool act = (p < end);

            // array 1
            int a1 = act ? i1[p] : -1;
            if ((unsigned)a1 >= MAX_ATOMS) a1 = -1;
            unsigned peers = __match_any_sync(0xFFFFFFFFu, a1);
            unsigned lower = peers & ((1u << lane) - 1u);
            int rank = __popc(lower);
            int slot = -1;
            if (a1 >= 0) slot = (int)(h[a1] & 0xFFFFu) + rank;
            __syncwarp();
            if (a1 >= 0 && lower == 0u) h[a1] += (unsigned)__popc(peers);
            __syncwarp();
            if (a1 >= 0 && slot < MAXC) {
                g_pair1[a1 * MAXC + slot] =
                    make_float4(d1[p], u1[3 * p + 0], u1[3 * p + 1], u1[3 * p + 2]);
            }

            // array 2
            int a2 = act ? i2[p] : -1;
            if ((unsigned)a2 >= MAX_ATOMS) a2 = -1;
            peers = __match_any_sync(0xFFFFFFFFu, a2);
            lower = peers & ((1u << lane) - 1u);
            rank = __popc(lower);
            slot = -1;
            if (a2 >= 0) slot = (int)(h[a2] >> 16) + rank;
            __syncwarp();
            if (a2 >= 0 && lower == 0u) h[a2] += ((unsigned)__popc(peers)) << 16;
            __syncwarp();
            if (a2 >= 0 && slot < MAXC) {
                g_pair2[a2 * MAXC + slot] =
                    make_float4(d2[p], u2[3 * p + 0], u2[3 * p + 1], u2[3 * p + 2]);
            }
        }
    }
}

// ---- K2: fused compute. Block = 16x16 atom tile, bucket rows in shared. ----
// Padded row stride (MAXC+1 float4 = 260 words = 4 mod 32 banks) makes the
// 16-distinct-row LDS.128 conflict-free per quarter-warp phase.
__global__ void __launch_bounds__(TI * TJ)
k_compute(const float* __restrict__ ls, float* __restrict__ out) {
    __shared__ float4 sP[TI][MAXC + 1];
    __shared__ float4 sQ[TJ][MAXC + 1];
    __shared__ int    sc1[TI];
    __shared__ int    sc2[TJ];

    int na1 = g_na1;
    int na2 = g_na2;
    int tiles_j = (na2 + TJ - 1) / TJ;
    int tiles_i = (na1 + TI - 1) / TI;
    int tile = blockIdx.x;
    if (tile >= tiles_i * tiles_j) return;
    int tile_i = tile / tiles_j;
    int tile_j = tile - tile_i * tiles_j;
    int ib = tile_i * TI;
    int jb = tile_j * TJ;

    int tid = threadIdx.x;
    if (tid < TI) {
        int ii = ib + tid;
        int c = (ii < na1) ? g_cnt1[ii] : 0;
        sc1[tid] = (c > MAXC) ? MAXC : c;
    } else if (tid < TI + TJ) {
        int jj = jb + (tid - TI);
        int c = (jj < na2) ? g_cnt2[jj] : 0;
        sc2[tid - TI] = (c > MAXC) ? MAXC : c;
    }
    __syncthreads();

    int r = tid >> 4;
    int s = tid & 15;
    for (int sl = s; sl < sc1[r]; sl += 16) sP[r][sl] = g_pair1[(ib + r) * MAXC + sl];
    for (int sl = s; sl < sc2[r]; sl += 16) sQ[r][sl] = g_pair2[(jb + r) * MAXC + sl];
    __syncthreads();

    int tx = tid & 15;               // j within tile
    int ty = tid >> 4;               // i within tile
    int i = ib + ty;
    int j = jb + tx;

    float l = ls[0];
    float inv_l2 = 1.0f / (l * l);
    float cc    = -0.72134752f * inv_l2;      // -0.5 * log2(e) * inv_l2
    float minv4 = -inv_l2 * inv_l2;

    int c1 = sc1[ty];
    int c2 = sc2[tx];

    float a00 = 0.f, a01 = 0.f, a02 = 0.f;
    float a10 = 0.f, a11 = 0.f, a12 = 0.f;
    float a20 = 0.f, a21 = 0.f, a22 = 0.f;

    for (int a = 0; a < c1; a++) {
        float4 pa = sP[ty][a];
        #pragma unroll 4
        for (int b = 0; b < c2; b++) {
            float4 qb = sQ[tx][b];
            float diff = pa.x - qb.x;
            float d2s  = diff * diff;
            float ex;
            asm("ex2.approx.f32 %0, %1;" : "=f"(ex) : "f"(cc * d2s));
            float w = fmaf(d2s, minv4, inv_l2);   // inv_l2 - d2s*inv_l2^2
            float g = w * ex;
            float gx = g * pa.y;
            float gy = g * pa.z;
            float gz = g * pa.w;
            a00 += gx * qb.y; a01 += gx * qb.z; a02 += gx * qb.w;
            a10 += gy * qb.y; a11 += gy * qb.z; a12 += gy * qb.w;
            a20 += gz * qb.y; a21 += gz * qb.z; a22 += gz * qb.w;
        }
    }

    if (i < na1 && j < na2) {
        int ld = 3 * na2;
        float* o0 = out + (3 * i + 0) * (long long)ld + 3 * j;
        float* o1 = o0 + ld;
        float* o2 = o1 + ld;
        o0[0] = a00; o0[1] = a01; o0[2] = a02;
        o1[0] = a10; o1[1] = a11; o1[2] = a12;
        o2[0] = a20; o2[1] = a21; o2[2] = a22;
    }
}

// ----------------------------------------------------------------------------
// Inputs (metadata order): d1[N], u1[N*3], d2[N], u2[N*3], lengthscale[1],
//                          i1[N], i2[N], [natoms1], [natoms2]
// Output: float[natoms1*3 * natoms2*3]
// ----------------------------------------------------------------------------
extern "C" void kernel_launch(void* const* d_in, const int* in_sizes, int n_in,
                              void* d_out, int out_size) {
    const float* d1 = (const float*)d_in[0];
    const float* u1 = (const float*)d_in[1];
    const float* d2 = (const float*)d_in[2];
    const float* u2 = (const float*)d_in[3];
    const float* ls = (const float*)d_in[4];
    const int*   i1 = (const int*)d_in[5];
    const int*   i2 = (const int*)d_in[6];
    const int*   na1p = (n_in >= 9) ? (const int*)d_in[7] : nullptr;
    const int*   na2p = (n_in >= 9) ? (const int*)d_in[8] : nullptr;

    int n_pairs = in_sizes[0];          // element count of d1 == N_PAIRS
    int tot = out_size / 9;             // na1 * na2

    // Tile-count upper bound for any (na1, na2) with na1*na2 = tot, na<=4096:
    // ceil(na1/16)*ceil(na2/16) <= tot/256 + (na1+na2)/16 + 1
    int max_tiles = (tot + TI * TJ - 1) / (TI * TJ) + 2 * MAX_ATOMS / 16 + 2;

    // 128KB dynamic smem for the per-warp histograms (within sm_103a's 228KB
    // carveout). Idempotent host-side attribute set: legal under graph capture.
    int prep_smem = PREP_WARPS * MAX_ATOMS * (int)sizeof(unsigned int);
    cudaFuncSetAttribute(k_prep, cudaFuncAttributeMaxDynamicSharedMemorySize,
                         prep_smem);

    k_prep<<<1, 512, prep_smem>>>(d1, u1, i1, d2, u2, i2,
                                  n_pairs, na1p, na2p, out_size);
    k_compute<<<max_tiles, TI * TJ>>>(ls, (float*)d_out);
}

// round 9
// speedup vs baseline: 2.7719x; 1.3881x over previous
#include <cuda_runtime.h>
#include <math.h>

// ----------------------------------------------------------------------------
// DSimilarity gradgrad: out[3i+a, 3j+b] = sum_{p: i1[p]=i, q: i2[q]=j}
//    gg(d1[p]-d2[q]) * u1[p,a] * u2[q,b]
// gg(x) = (inv_l2 - x^2 inv_l2^2) * exp(-0.5 x^2 inv_l2)
//
// k_prep    : deterministic counting sort; grid=2, block 0 buckets array 1,
//             block 1 buckets array 2 (independent -> 2 SMs in parallel).
// k_compute : 16x16 atom tile per block, bucket rows staged in padded shared
//             memory; inner loop factorized as v[y] = sum_b g * q[y] then
//             9 FFMA per a (outer product pulled out of the b-loop).
// ----------------------------------------------------------------------------

#define MAX_ATOMS  4096
#define MAXC       64          // bucket capacity (mean count ~8)
#define PREP_WARPS 8
#define TI         16
#define TJ         16

__device__ int    g_na1;
__device__ int    g_na2;
__device__ int    g_cnt1[MAX_ATOMS];
__device__ int    g_cnt2[MAX_ATOMS];
__device__ float4 g_pair1[MAX_ATOMS * MAXC];   // (d, ux, uy, uz) bucketed by i1
__device__ float4 g_pair2[MAX_ATOMS * MAXC];   // bucketed by i2

// ---- K1: deterministic bucket build. Two blocks, 512 threads each. ----
// Block 0: (d1,u1,i1) -> g_pair1/g_cnt1.  Block 1: (d2,u2,i2) -> g_pair2/g_cnt2.
// hist[w][atom] = count for warp w's p-range of this block's array.
__global__ void __launch_bounds__(512)
k_prep(const float* __restrict__ d1, const float* __restrict__ u1,
       const int* __restrict__ i1,
       const float* __restrict__ d2, const float* __restrict__ u2,
       const int* __restrict__ i2,
       int n, const int* na1p, const int* na2p, int out_size) {
    extern __shared__ unsigned int hist[];   // [PREP_WARPS][MAX_ATOMS]

    int tid = threadIdx.x;
    int arr = blockIdx.x;                    // 0 or 1

    const float* dd   = arr ? d2 : d1;
    const float* uu   = arr ? u2 : u1;
    const int*   ii   = arr ? i2 : i1;
    int*         gcnt = arr ? g_cnt2 : g_cnt1;
    float4*      gp   = arr ? g_pair2 : g_pair1;

    if (arr == 0 && tid == 0) {
        int na1, na2;
        if (na1p != nullptr && na2p != nullptr) {
            na1 = *na1p;
            na2 = *na2p;
        } else {
            int tot = out_size / 9;
            int r = (int)(sqrtf((float)tot) + 0.5f);
            while (r > 0 && r * r > tot) r--;
            while ((r + 1) * (r + 1) <= tot) r++;
            na1 = r; na2 = r;
        }
        if (na1 < 1) na1 = 1;  if (na1 > MAX_ATOMS) na1 = MAX_ATOMS;
        if (na2 < 1) na2 = 1;  if (na2 > MAX_ATOMS) na2 = MAX_ATOMS;
        g_na1 = na1;
        g_na2 = na2;
    }

    for (int t = tid; t < PREP_WARPS * MAX_ATOMS; t += 512) hist[t] = 0u;
    __syncthreads();

    int wid  = tid >> 5;
    int lane = tid & 31;
    int range = (n + PREP_WARPS - 1) / PREP_WARPS;
    int start = wid * range;
    int end   = start + range; if (end > n) end = n;

    // ---- Phase 1: per-warp histograms (order-independent atomics) ----
    if (wid < PREP_WARPS) {
        unsigned int* h = &hist[wid * MAX_ATOMS];
        for (int p0 = start; p0 < end; p0 += 32) {
            int p = p0 + lane;
            if (p < end) {
                unsigned a = (unsigned)ii[p];
                if (a < MAX_ATOMS) atomicAdd(&h[a], 1u);
            }
        }
    }
    __syncthreads();

    // ---- Phase 2: exclusive prefix across warps per atom; totals to gcnt ----
    for (int atom = tid; atom < MAX_ATOMS; atom += 512) {
        unsigned run = 0;
        #pragma unroll
        for (int w = 0; w < PREP_WARPS; w++) {
            unsigned v = hist[w * MAX_ATOMS + atom];
            hist[w * MAX_ATOMS + atom] = run;
            run += v;
        }
        gcnt[atom] = (int)run;
    }
    __syncthreads();

    // ---- Phase 3: deterministic placement (stable = ascending p) ----
    if (wid < PREP_WARPS) {
        unsigned int* h = &hist[wid * MAX_ATOMS];
        for (int p0 = start; p0 < end; p0 += 32) {
            int p = p0 + lane;
            bool act = (p < end);
            int a = act ? ii[p] : -1;
            if ((unsigned)a >= MAX_ATOMS) a = -1;
            unsigned peers = __match_any_sync(0xFFFFFFFFu, a);
            unsigned lower = peers & ((1u << lane) - 1u);
            int rank = __popc(lower);
            int slot = -1;
            if (a >= 0) slot = (int)h[a] + rank;
            __syncwarp();
            if (a >= 0 && lower == 0u) h[a] += (unsigned)__popc(peers);
            __syncwarp();
            if (a >= 0 && slot < MAXC) {
                gp[a * MAXC + slot] =
                    make_float4(dd[p], uu[3 * p + 0], uu[3 * p + 1], uu[3 * p + 2]);
            }
        }
    }
}

// ---- K2: fused compute. Block = 16x16 atom tile, bucket rows in shared. ----
// Padded row stride (MAXC+1 float4 = 260 words = 4 mod 32 banks) keeps the
// 16-distinct-row LDS.128 conflict-free per quarter-warp phase.
// Inner loop factorized: v[y] = sum_b g(a,b)*q[y]; then out_xy += p[x]*v[y].
__global__ void __launch_bounds__(TI * TJ)
k_compute(const float* __restrict__ ls, float* __restrict__ out) {
    __shared__ float4 sP[TI][MAXC + 1];
    __shared__ float4 sQ[TJ][MAXC + 1];
    __shared__ int    sc1[TI];
    __shared__ int    sc2[TJ];

    int na1 = g_na1;
    int na2 = g_na2;
    int tiles_j = (na2 + TJ - 1) / TJ;
    int tiles_i = (na1 + TI - 1) / TI;
    int tile = blockIdx.x;
    if (tile >= tiles_i * tiles_j) return;
    int tile_i = tile / tiles_j;
    int tile_j = tile - tile_i * tiles_j;
    int ib = tile_i * TI;
    int jb = tile_j * TJ;

    int tid = threadIdx.x;
    if (tid < TI) {
        int ii = ib + tid;
        int c = (ii < na1) ? g_cnt1[ii] : 0;
        sc1[tid] = (c > MAXC) ? MAXC : c;
    } else if (tid < TI + TJ) {
        int jj = jb + (tid - TI);
        int c = (jj < na2) ? g_cnt2[jj] : 0;
        sc2[tid - TI] = (c > MAXC) ? MAXC : c;
    }
    __syncthreads();

    int r = tid >> 4;
    int s = tid & 15;
    for (int sl = s; sl < sc1[r]; sl += 16) sP[r][sl] = g_pair1[(ib + r) * MAXC + sl];
    for (int sl = s; sl < sc2[r]; sl += 16) sQ[r][sl] = g_pair2[(jb + r) * MAXC + sl];
    __syncthreads();

    int tx = tid & 15;               // j within tile
    int ty = tid >> 4;               // i within tile
    int i = ib + ty;
    int j = jb + tx;

    float l = ls[0];
    float inv_l2 = 1.0f / (l * l);
    float cc    = -0.72134752f * inv_l2;      // -0.5 * log2(e) * inv_l2
    float minv4 = -inv_l2 * inv_l2;

    int c1 = sc1[ty];
    int c2 = sc2[tx];

    float a00 = 0.f, a01 = 0.f, a02 = 0.f;
    float a10 = 0.f, a11 = 0.f, a12 = 0.f;
    float a20 = 0.f, a21 = 0.f, a22 = 0.f;

    for (int a = 0; a < c1; a++) {
        float4 pa = sP[ty][a];
        float vx = 0.f, vy = 0.f, vz = 0.f;
        #pragma unroll 4
        for (int b = 0; b < c2; b++) {
            float4 qb = sQ[tx][b];
            float diff = pa.x - qb.x;
            float d2s  = diff * diff;
            float ex;
            asm("ex2.approx.f32 %0, %1;" : "=f"(ex) : "f"(cc * d2s));
            float w = fmaf(d2s, minv4, inv_l2);   // inv_l2 - d2s*inv_l2^2
            float g = w * ex;
            vx += g * qb.y;
            vy += g * qb.z;
            vz += g * qb.w;
        }
        a00 += pa.y * vx; a01 += pa.y * vy; a02 += pa.y * vz;
        a10 += pa.z * vx; a11 += pa.z * vy; a12 += pa.z * vz;
        a20 += pa.w * vx; a21 += pa.w * vy; a22 += pa.w * vz;
    }

    if (i < na1 && j < na2) {
        int ld = 3 * na2;
        float* o0 = out + (3 * i + 0) * (long long)ld + 3 * j;
        float* o1 = o0 + ld;
        float* o2 = o1 + ld;
        o0[0] = a00; o0[1] = a01; o0[2] = a02;
        o1[0] = a10; o1[1] = a11; o1[2] = a12;
        o2[0] = a20; o2[1] = a21; o2[2] = a22;
    }
}

// ----------------------------------------------------------------------------
// Inputs (metadata order): d1[N], u1[N*3], d2[N], u2[N*3], lengthscale[1],
//                          i1[N], i2[N], [natoms1], [natoms2]
// Output: float[natoms1*3 * natoms2*3]
// ----------------------------------------------------------------------------
extern "C" void kernel_launch(void* const* d_in, const int* in_sizes, int n_in,
                              void* d_out, int out_size) {
    const float* d1 = (const float*)d_in[0];
    const float* u1 = (const float*)d_in[1];
    const float* d2 = (const float*)d_in[2];
    const float* u2 = (const float*)d_in[3];
    const float* ls = (const float*)d_in[4];
    const int*   i1 = (const int*)d_in[5];
    const int*   i2 = (const int*)d_in[6];
    const int*   na1p = (n_in >= 9) ? (const int*)d_in[7] : nullptr;
    const int*   na2p = (n_in >= 9) ? (const int*)d_in[8] : nullptr;

    int n_pairs = in_sizes[0];          // element count of d1 == N_PAIRS
    int tot = out_size / 9;             // na1 * na2

    // Tile-count upper bound for any (na1, na2) with na1*na2 = tot, na<=4096:
    // ceil(na1/16)*ceil(na2/16) <= tot/256 + (na1+na2)/16 + 1
    int max_tiles = (tot + TI * TJ - 1) / (TI * TJ) + 2 * MAX_ATOMS / 16 + 2;

    // 128KB dynamic smem for the per-warp histograms (within sm_103a's 228KB
    // carveout). Idempotent host-side attribute set: legal under graph capture.
    int prep_smem = PREP_WARPS * MAX_ATOMS * (int)sizeof(unsigned int);
    cudaFuncSetAttribute(k_prep, cudaFuncAttributeMaxDynamicSharedMemorySize,
                         prep_smem);

    k_prep<<<2, 512, prep_smem>>>(d1, u1, i1, d2, u2, i2,
                                  n_pairs, na1p, na2p, out_size);
    k_compute<<<max_tiles, TI * TJ>>>(ls, (float*)d_out);
}